// round 1
// baseline (speedup 1.0000x reference)
#include <cuda_runtime.h>
#include <math.h>

// Problem constants
#define B_  2
#define S_  1024
#define D_  1024
#define H_  16
#define DH_ 64
#define BH_ (B_ * H_)          // 32
#define M_  (B_ * S_)          // 2048

// ---------------------------------------------------------------------------
// Scratch (static device globals; no allocation allowed)
// ---------------------------------------------------------------------------
__device__ float g_proj[5ull * M_ * D_];          // q,k,v,qr,kr : 40MB
__device__ float g_scores[(size_t)BH_ * S_ * S_]; // 128MB (scores -> attn in place)
__device__ float g_ctx[(size_t)M_ * D_];          // 8MB

// ---------------------------------------------------------------------------
// SGEMM: C = A * B^T + bias.  A:(M,K) row-major, B:(N,K) row-major.
// 128x128 tile, BK=8, 256 threads, 8x8 micro-tile.
// mode 0: scatter into (B,H,S,DH) layout; mode 1: plain row-major (M,N).
// ---------------------------------------------------------------------------
__global__ __launch_bounds__(256)
void sgemm_abt(const float* __restrict__ A, const float* __restrict__ Bm,
               const float* __restrict__ bias, float* __restrict__ C,
               int M, int N, int K, int mode)
{
    __shared__ float As[8][128];
    __shared__ float Bs[8][128];

    int tid = threadIdx.x;
    int tx = tid & 15, ty = tid >> 4;
    int m0 = blockIdx.y * 128, n0 = blockIdx.x * 128;

    int arow = tid >> 1;          // 0..127
    int kg   = (tid & 1) * 4;     // 0 or 4

    const float* Aptr = A  + (size_t)(m0 + arow) * K + kg;
    const float* Bptr = Bm + (size_t)(n0 + arow) * K + kg;

    float acc[8][8];
#pragma unroll
    for (int i = 0; i < 8; i++)
#pragma unroll
        for (int j = 0; j < 8; j++) acc[i][j] = 0.f;

    for (int k0 = 0; k0 < K; k0 += 8) {
        float4 av = *(const float4*)(Aptr + k0);
        float4 bv = *(const float4*)(Bptr + k0);
        As[kg + 0][arow] = av.x; As[kg + 1][arow] = av.y;
        As[kg + 2][arow] = av.z; As[kg + 3][arow] = av.w;
        Bs[kg + 0][arow] = bv.x; Bs[kg + 1][arow] = bv.y;
        Bs[kg + 2][arow] = bv.z; Bs[kg + 3][arow] = bv.w;
        __syncthreads();

#pragma unroll
        for (int kk = 0; kk < 8; kk++) {
            float4 a0 = *(const float4*)&As[kk][ty * 8];
            float4 a1 = *(const float4*)&As[kk][ty * 8 + 4];
            float4 b0 = *(const float4*)&Bs[kk][tx * 8];
            float4 b1 = *(const float4*)&Bs[kk][tx * 8 + 4];
            float a[8] = {a0.x, a0.y, a0.z, a0.w, a1.x, a1.y, a1.z, a1.w};
            float b[8] = {b0.x, b0.y, b0.z, b0.w, b1.x, b1.y, b1.z, b1.w};
#pragma unroll
            for (int i = 0; i < 8; i++)
#pragma unroll
                for (int j = 0; j < 8; j++)
                    acc[i][j] += a[i] * b[j];
        }
        __syncthreads();
    }

#pragma unroll
    for (int i = 0; i < 8; i++) {
        int m = m0 + ty * 8 + i;
#pragma unroll
        for (int j = 0; j < 8; j++) {
            int n = n0 + tx * 8 + j;
            float v = acc[i][j] + bias[n];
            if (mode == 0) {
                int b = m >> 10, s = m & 1023;
                int h = n >> 6,  dh = n & 63;
                C[(((size_t)(b * H_ + h) << 10) + s) * DH_ + dh] = v;
            } else {
                C[(size_t)m * N + n] = v;
            }
        }
    }
}

// ---------------------------------------------------------------------------
// Fused scores: scores[bh,i,j] = (q_i.k_j + q_i.kr_p + qr_p.k_j) / sqrt(192)
// p = clamp(i - j + 512, 0, 1023). 64x64 output tile per block; gathered
// kr/qr rows for the tile span exactly 127 relative positions -> staged in smem.
// ---------------------------------------------------------------------------
__global__ __launch_bounds__(256)
void scores_kernel(const float* __restrict__ q, const float* __restrict__ k,
                   const float* __restrict__ qr, const float* __restrict__ kr,
                   float* __restrict__ scores)
{
    extern __shared__ float sm[];
    float* Qs  = sm;                    // 64 * 65
    float* Ks  = Qs  + 64 * 65;         // 64 * 65
    float* KRs = Ks  + 64 * 65;         // 127 * 65
    float* QRs = KRs + 127 * 65;        // 127 * 65

    int bh = blockIdx.z;
    int i0 = blockIdx.y * 64, j0 = blockIdx.x * 64;
    const float* qp  = q  + (size_t)bh * S_ * DH_;
    const float* kp  = k  + (size_t)bh * S_ * DH_;
    const float* qrp = qr + (size_t)bh * S_ * DH_;
    const float* krp = kr + (size_t)bh * S_ * DH_;

    int tid = threadIdx.x;

    // load Q/K tiles (64 rows x 64 cols each)
    for (int f = tid; f < 64 * 16; f += 256) {
        int r = f >> 4, c = (f & 15) << 2;
        float4 v = *(const float4*)(qp + (size_t)(i0 + r) * DH_ + c);
        Qs[r * 65 + c + 0] = v.x; Qs[r * 65 + c + 1] = v.y;
        Qs[r * 65 + c + 2] = v.z; Qs[r * 65 + c + 3] = v.w;
        float4 w = *(const float4*)(kp + (size_t)(j0 + r) * DH_ + c);
        Ks[r * 65 + c + 0] = w.x; Ks[r * 65 + c + 1] = w.y;
        Ks[r * 65 + c + 2] = w.z; Ks[r * 65 + c + 3] = w.w;
    }

    // gathered relative rows: raw p = i - j + 512 spans [p0, p0+126]
    int p0 = i0 - j0 + 449;
    for (int f = tid; f < 127 * 16; f += 256) {
        int t = f >> 4, c = (f & 15) << 2;
        int pr = p0 + t;
        pr = pr < 0 ? 0 : (pr > 1023 ? 1023 : pr);
        float4 v = *(const float4*)(krp + (size_t)pr * DH_ + c);
        KRs[t * 65 + c + 0] = v.x; KRs[t * 65 + c + 1] = v.y;
        KRs[t * 65 + c + 2] = v.z; KRs[t * 65 + c + 3] = v.w;
        float4 w = *(const float4*)(qrp + (size_t)pr * DH_ + c);
        QRs[t * 65 + c + 0] = w.x; QRs[t * 65 + c + 1] = w.y;
        QRs[t * 65 + c + 2] = w.z; QRs[t * 65 + c + 3] = w.w;
    }
    __syncthreads();

    int tx = tid & 15, ty = tid >> 4;
    int ib = ty * 4, jb = tx * 4;
    int tb = ib - jb + 63;    // local rel index for (ii=0,jj=0); tb-3..tb+3 in [0,126]

    float acc[4][4];
#pragma unroll
    for (int a = 0; a < 4; a++)
#pragma unroll
        for (int b = 0; b < 4; b++) acc[a][b] = 0.f;

#pragma unroll 4
    for (int d = 0; d < 64; d++) {
        float qv[4], kv[4], krv[7], qrv[7];
#pragma unroll
        for (int ii = 0; ii < 4; ii++) qv[ii] = Qs[(ib + ii) * 65 + d];
#pragma unroll
        for (int jj = 0; jj < 4; jj++) kv[jj] = Ks[(jb + jj) * 65 + d];
#pragma unroll
        for (int u = 0; u < 7; u++) {
            krv[u] = KRs[(tb - 3 + u) * 65 + d];
            qrv[u] = QRs[(tb - 3 + u) * 65 + d];
        }
#pragma unroll
        for (int ii = 0; ii < 4; ii++)
#pragma unroll
            for (int jj = 0; jj < 4; jj++) {
                int u = ii - jj + 3;
                acc[ii][jj] += qv[ii] * (kv[jj] + krv[u]) + qrv[u] * kv[jj];
            }
    }

    const float inv = 0.07216878364870323f;   // 1/sqrt(192)
    float* sp = scores + (size_t)bh * S_ * S_;
#pragma unroll
    for (int ii = 0; ii < 4; ii++)
#pragma unroll
        for (int jj = 0; jj < 4; jj++)
            sp[(size_t)(i0 + ib + ii) * S_ + (j0 + jb + jj)] = acc[ii][jj] * inv;
}

// ---------------------------------------------------------------------------
// Row softmax with padding mask (in place on scores)
// ---------------------------------------------------------------------------
__global__ __launch_bounds__(256)
void softmax_kernel(float* __restrict__ scores, const int* __restrict__ mask)
{
    int row = blockIdx.x;                 // bh * S + i
    int b = row >> 14;                    // row / (H*S)
    float* sp = scores + (size_t)row * S_;
    const int* mp = mask + b * S_;
    int tid = threadIdx.x;

    __shared__ float red[256];

    float vals[4];
    float mx = -INFINITY;
#pragma unroll
    for (int u = 0; u < 4; u++) {
        int j = tid + u * 256;
        float v = sp[j];
        if (mp[j] == 1) v = -INFINITY;
        vals[u] = v;
        mx = fmaxf(mx, v);
    }
    red[tid] = mx; __syncthreads();
    for (int s = 128; s > 0; s >>= 1) {
        if (tid < s) red[tid] = fmaxf(red[tid], red[tid + s]);
        __syncthreads();
    }
    mx = red[0];
    __syncthreads();

    float sum = 0.f;
#pragma unroll
    for (int u = 0; u < 4; u++) {
        vals[u] = __expf(vals[u] - mx);
        sum += vals[u];
    }
    red[tid] = sum; __syncthreads();
    for (int s = 128; s > 0; s >>= 1) {
        if (tid < s) red[tid] += red[tid + s];
        __syncthreads();
    }
    float r = 1.f / red[0];
#pragma unroll
    for (int u = 0; u < 4; u++)
        sp[tid + u * 256] = vals[u] * r;
}

// ---------------------------------------------------------------------------
// AV: ctx[b, i, h*64+d] = sum_j attn[bh,i,j] * v[bh,j,d]
// 64(i) x 64(d) tile per block, BK = 32
// ---------------------------------------------------------------------------
__global__ __launch_bounds__(256)
void av_kernel(const float* __restrict__ attn, const float* __restrict__ v,
               float* __restrict__ ctx)
{
    __shared__ float As[64][33];
    __shared__ float Bs[32][64];

    int bh = blockIdx.y;
    int i0 = blockIdx.x * 64;
    const float* ap = attn + (size_t)bh * S_ * S_;
    const float* vp = v    + (size_t)bh * S_ * DH_;
    int tid = threadIdx.x;
    int tx = tid & 15, ty = tid >> 4;
    int ib = ty * 4, jb = tx * 4;

    float acc[4][4];
#pragma unroll
    for (int a = 0; a < 4; a++)
#pragma unroll
        for (int b = 0; b < 4; b++) acc[a][b] = 0.f;

    for (int k0 = 0; k0 < S_; k0 += 32) {
        for (int f = tid; f < 64 * 8; f += 256) {
            int r = f >> 3, c = (f & 7) << 2;
            float4 x = *(const float4*)(ap + (size_t)(i0 + r) * S_ + k0 + c);
            As[r][c + 0] = x.x; As[r][c + 1] = x.y;
            As[r][c + 2] = x.z; As[r][c + 3] = x.w;
        }
        for (int f = tid; f < 32 * 16; f += 256) {
            int r = f >> 4, c = (f & 15) << 2;
            float4 x = *(const float4*)(vp + (size_t)(k0 + r) * DH_ + c);
            *(float4*)&Bs[r][c] = x;
        }
        __syncthreads();

#pragma unroll 8
        for (int kk = 0; kk < 32; kk++) {
            float avv[4], bvv[4];
#pragma unroll
            for (int ii = 0; ii < 4; ii++) avv[ii] = As[ib + ii][kk];
            float4 bq = *(const float4*)&Bs[kk][jb];
            bvv[0] = bq.x; bvv[1] = bq.y; bvv[2] = bq.z; bvv[3] = bq.w;
#pragma unroll
            for (int ii = 0; ii < 4; ii++)
#pragma unroll
                for (int jj = 0; jj < 4; jj++)
                    acc[ii][jj] += avv[ii] * bvv[jj];
        }
        __syncthreads();
    }

    int b = bh >> 4, h = bh & 15;
#pragma unroll
    for (int ii = 0; ii < 4; ii++)
#pragma unroll
        for (int jj = 0; jj < 4; jj++)
            ctx[((size_t)(b * S_ + i0 + ib + ii)) * D_ + h * DH_ + jb + jj] = acc[ii][jj];
}

// ---------------------------------------------------------------------------
// Launch
// ---------------------------------------------------------------------------
extern "C" void kernel_launch(void* const* d_in, const int* in_sizes, int n_in,
                              void* d_out, int out_size)
{
    const float* x    = (const float*)d_in[0];
    const float* rel  = (const float*)d_in[1];
    const int*   pmask= (const int*)  d_in[2];
    const float* Wq   = (const float*)d_in[3];
    const float* bq   = (const float*)d_in[4];
    const float* Wk   = (const float*)d_in[5];
    const float* bk   = (const float*)d_in[6];
    const float* Wv   = (const float*)d_in[7];
    const float* bv   = (const float*)d_in[8];
    const float* Wqr  = (const float*)d_in[9];
    const float* bqr  = (const float*)d_in[10];
    const float* Wkr  = (const float*)d_in[11];
    const float* bkr  = (const float*)d_in[12];
    const float* Wc   = (const float*)d_in[13];
    const float* bc   = (const float*)d_in[14];
    float* out = (float*)d_out;

    float *proj_base, *scores, *ctx;
    cudaGetSymbolAddress((void**)&proj_base, g_proj);
    cudaGetSymbolAddress((void**)&scores, g_scores);
    cudaGetSymbolAddress((void**)&ctx, g_ctx);

    const size_t P = (size_t)M_ * D_;   // 2M floats
    float* q  = proj_base + 0 * P;
    float* k  = proj_base + 1 * P;
    float* v  = proj_base + 2 * P;
    float* qr = proj_base + 3 * P;
    float* kr = proj_base + 4 * P;

    // raise dynamic smem limit for scores kernel (idempotent)
    const int SC_SMEM = (64 * 65 * 2 + 127 * 65 * 2) * 4;  // 99,320 bytes
    cudaFuncSetAttribute(scores_kernel,
                         cudaFuncAttributeMaxDynamicSharedMemorySize, SC_SMEM);

    dim3 gGemm(D_ / 128, M_ / 128);   // (8, 16)

    // 5 projections (scatter to (B,H,S,DH))
    sgemm_abt<<<gGemm, 256>>>(x,   Wq,  bq,  q,  M_, D_, D_, 0);
    sgemm_abt<<<gGemm, 256>>>(x,   Wk,  bk,  k,  M_, D_, D_, 0);
    sgemm_abt<<<gGemm, 256>>>(x,   Wv,  bv,  v,  M_, D_, D_, 0);
    sgemm_abt<<<gGemm, 256>>>(rel, Wqr, bqr, qr, M_, D_, D_, 0);
    sgemm_abt<<<gGemm, 256>>>(rel, Wkr, bkr, kr, M_, D_, D_, 0);

    // fused disentangled scores
    dim3 gSc(S_ / 64, S_ / 64, BH_);  // (16,16,32)
    scores_kernel<<<gSc, 256, SC_SMEM>>>(q, k, qr, kr, scores);

    // softmax + mask (in place)
    softmax_kernel<<<BH_ * S_, 256>>>(scores, pmask);

    // attn @ V -> ctx (B,S,D)
    dim3 gAv(S_ / 64, BH_);           // (16,32)
    av_kernel<<<gAv, 256>>>(scores, v, ctx);

    // output projection
    sgemm_abt<<<gGemm, 256>>>(ctx, Wc, bc, out, M_, D_, D_, 1);
}

// round 2
// speedup vs baseline: 1.5896x; 1.5896x over previous
#include <cuda_runtime.h>
#include <math.h>
#include <stdint.h>

// Problem constants
#define B_  2
#define S_  1024
#define D_  1024
#define H_  16
#define DH_ 64
#define BH_ (B_ * H_)          // 32
#define M_  (B_ * S_)          // 2048

// ---------------------------------------------------------------------------
// Scratch (static device globals; no allocation allowed)
// ---------------------------------------------------------------------------
__device__ float g_proj[5ull * M_ * D_];          // q,k,v,qr,kr : 40MB
__device__ float g_scores[(size_t)BH_ * S_ * S_]; // 128MB (scores -> attn in place)
__device__ float g_ctx[(size_t)M_ * D_];          // 8MB

// ---------------------------------------------------------------------------
// tf32 helpers
// ---------------------------------------------------------------------------
__device__ __forceinline__ float to_tf32(float x) {
    uint32_t u = __float_as_uint(x);
    uint32_t y;
    asm("cvt.rna.tf32.f32 %0, %1;" : "=r"(y) : "r"(u));
    return __uint_as_float(y);
}

// ---------------------------------------------------------------------------
// TF32 tensor-core GEMM: C = A * B^T + bias.
// A:(M,K) row-major, B:(N,K) row-major. 128x128 tile, BK=16, 256 threads,
// 8 warps in 2(m) x 4(n) grid, each warp 64x32 via 4x4 m16n8k8 mma tiles.
// mode 0: scatter into (B,H,S,DH) layout; mode 1: plain row-major (M,N).
// ---------------------------------------------------------------------------
__global__ __launch_bounds__(256)
void gemm_tf32(const float* __restrict__ A, const float* __restrict__ Bm,
               const float* __restrict__ bias, float* __restrict__ C,
               int K, int N, int mode)
{
    __shared__ float As[128][20];   // [m][k], stride 20 -> conflict-free frag loads
    __shared__ float Bs[128][20];   // [n][k]

    int tid  = threadIdx.x;
    int warp = tid >> 5;
    int lane = tid & 31;
    int g    = lane >> 2;      // groupID
    int tig  = lane & 3;       // thread-in-group

    int wm = warp >> 2;        // 0..1  (64-row slab)
    int wn = warp & 3;         // 0..3  (32-col slab)

    int m0 = blockIdx.y * 128, n0 = blockIdx.x * 128;

    // global load mapping: each thread does 2 rows x 1 float4 per matrix
    int lr  = tid >> 2;            // 0..63
    int lc4 = (tid & 3) << 2;      // 0,4,8,12

    float acc[4][4][4];            // [mt][nt][frag]
#pragma unroll
    for (int a = 0; a < 4; a++)
#pragma unroll
        for (int b = 0; b < 4; b++)
#pragma unroll
            for (int c = 0; c < 4; c++) acc[a][b][c] = 0.f;

    for (int k0 = 0; k0 < K; k0 += 16) {
#pragma unroll
        for (int p = 0; p < 2; p++) {
            int r = lr + p * 64;
            float4 av = *(const float4*)(A  + (size_t)(m0 + r) * K + k0 + lc4);
            float4 bv = *(const float4*)(Bm + (size_t)(n0 + r) * K + k0 + lc4);
            As[r][lc4 + 0] = to_tf32(av.x); As[r][lc4 + 1] = to_tf32(av.y);
            As[r][lc4 + 2] = to_tf32(av.z); As[r][lc4 + 3] = to_tf32(av.w);
            Bs[r][lc4 + 0] = to_tf32(bv.x); Bs[r][lc4 + 1] = to_tf32(bv.y);
            Bs[r][lc4 + 2] = to_tf32(bv.z); Bs[r][lc4 + 3] = to_tf32(bv.w);
        }
        __syncthreads();

#pragma unroll
        for (int ks = 0; ks < 16; ks += 8) {
            uint32_t af[4][4];
            uint32_t bf[4][2];
#pragma unroll
            for (int mt = 0; mt < 4; mt++) {
                int rb = wm * 64 + mt * 16;
                af[mt][0] = __float_as_uint(As[rb + g    ][ks + tig    ]);
                af[mt][1] = __float_as_uint(As[rb + g + 8][ks + tig    ]);
                af[mt][2] = __float_as_uint(As[rb + g    ][ks + tig + 4]);
                af[mt][3] = __float_as_uint(As[rb + g + 8][ks + tig + 4]);
            }
#pragma unroll
            for (int nt = 0; nt < 4; nt++) {
                int cb = wn * 32 + nt * 8;
                bf[nt][0] = __float_as_uint(Bs[cb + g][ks + tig    ]);
                bf[nt][1] = __float_as_uint(Bs[cb + g][ks + tig + 4]);
            }
#pragma unroll
            for (int mt = 0; mt < 4; mt++)
#pragma unroll
                for (int nt = 0; nt < 4; nt++) {
                    asm volatile(
                        "mma.sync.aligned.m16n8k8.row.col.f32.tf32.tf32.f32 "
                        "{%0,%1,%2,%3}, {%4,%5,%6,%7}, {%8,%9}, {%0,%1,%2,%3};"
                        : "+f"(acc[mt][nt][0]), "+f"(acc[mt][nt][1]),
                          "+f"(acc[mt][nt][2]), "+f"(acc[mt][nt][3])
                        : "r"(af[mt][0]), "r"(af[mt][1]),
                          "r"(af[mt][2]), "r"(af[mt][3]),
                          "r"(bf[nt][0]), "r"(bf[nt][1]));
                }
        }
        __syncthreads();
    }

    // epilogue
#pragma unroll
    for (int mt = 0; mt < 4; mt++) {
#pragma unroll
        for (int nt = 0; nt < 4; nt++) {
#pragma unroll
            for (int fr = 0; fr < 4; fr++) {
                int m = m0 + wm * 64 + mt * 16 + g + (fr >> 1) * 8;
                int n = n0 + wn * 32 + nt * 8 + tig * 2 + (fr & 1);
                float v = acc[mt][nt][fr] + bias[n];
                if (mode == 0) {
                    int b = m >> 10, s = m & 1023;
                    int h = n >> 6,  dh = n & 63;
                    C[(((size_t)(b * H_ + h) << 10) + s) * DH_ + dh] = v;
                } else {
                    C[(size_t)m * N + n] = v;
                }
            }
        }
    }
}

// ---------------------------------------------------------------------------
// Fused scores: scores[bh,i,j] = (q_i.k_j + q_i.kr_p + qr_p.k_j) / sqrt(192)
// p = clamp(i - j + 512, 0, 1023). 64x64 output tile per block; gathered
// kr/qr rows for the tile span exactly 127 relative positions -> staged in smem.
// ---------------------------------------------------------------------------
__global__ __launch_bounds__(256)
void scores_kernel(const float* __restrict__ q, const float* __restrict__ k,
                   const float* __restrict__ qr, const float* __restrict__ kr,
                   float* __restrict__ scores)
{
    extern __shared__ float sm[];
    float* Qs  = sm;                    // 64 * 65
    float* Ks  = Qs  + 64 * 65;         // 64 * 65
    float* KRs = Ks  + 64 * 65;         // 127 * 65
    float* QRs = KRs + 127 * 65;        // 127 * 65

    int bh = blockIdx.z;
    int i0 = blockIdx.y * 64, j0 = blockIdx.x * 64;
    const float* qp  = q  + (size_t)bh * S_ * DH_;
    const float* kp  = k  + (size_t)bh * S_ * DH_;
    const float* qrp = qr + (size_t)bh * S_ * DH_;
    const float* krp = kr + (size_t)bh * S_ * DH_;

    int tid = threadIdx.x;

    for (int f = tid; f < 64 * 16; f += 256) {
        int r = f >> 4, c = (f & 15) << 2;
        float4 v = *(const float4*)(qp + (size_t)(i0 + r) * DH_ + c);
        Qs[r * 65 + c + 0] = v.x; Qs[r * 65 + c + 1] = v.y;
        Qs[r * 65 + c + 2] = v.z; Qs[r * 65 + c + 3] = v.w;
        float4 w = *(const float4*)(kp + (size_t)(j0 + r) * DH_ + c);
        Ks[r * 65 + c + 0] = w.x; Ks[r * 65 + c + 1] = w.y;
        Ks[r * 65 + c + 2] = w.z; Ks[r * 65 + c + 3] = w.w;
    }

    int p0 = i0 - j0 + 449;
    for (int f = tid; f < 127 * 16; f += 256) {
        int t = f >> 4, c = (f & 15) << 2;
        int pr = p0 + t;
        pr = pr < 0 ? 0 : (pr > 1023 ? 1023 : pr);
        float4 v = *(const float4*)(krp + (size_t)pr * DH_ + c);
        KRs[t * 65 + c + 0] = v.x; KRs[t * 65 + c + 1] = v.y;
        KRs[t * 65 + c + 2] = v.z; KRs[t * 65 + c + 3] = v.w;
        float4 w = *(const float4*)(qrp + (size_t)pr * DH_ + c);
        QRs[t * 65 + c + 0] = w.x; QRs[t * 65 + c + 1] = w.y;
        QRs[t * 65 + c + 2] = w.z; QRs[t * 65 + c + 3] = w.w;
    }
    __syncthreads();

    int tx = tid & 15, ty = tid >> 4;
    int ib = ty * 4, jb = tx * 4;
    int tb = ib - jb + 63;

    float acc[4][4];
#pragma unroll
    for (int a = 0; a < 4; a++)
#pragma unroll
        for (int b = 0; b < 4; b++) acc[a][b] = 0.f;

#pragma unroll 4
    for (int d = 0; d < 64; d++) {
        float qv[4], kv[4], krv[7], qrv[7];
#pragma unroll
        for (int ii = 0; ii < 4; ii++) qv[ii] = Qs[(ib + ii) * 65 + d];
#pragma unroll
        for (int jj = 0; jj < 4; jj++) kv[jj] = Ks[(jb + jj) * 65 + d];
#pragma unroll
        for (int u = 0; u < 7; u++) {
            krv[u] = KRs[(tb - 3 + u) * 65 + d];
            qrv[u] = QRs[(tb - 3 + u) * 65 + d];
        }
#pragma unroll
        for (int ii = 0; ii < 4; ii++)
#pragma unroll
            for (int jj = 0; jj < 4; jj++) {
                int u = ii - jj + 3;
                acc[ii][jj] += qv[ii] * (kv[jj] + krv[u]) + qrv[u] * kv[jj];
            }
    }

    const float inv = 0.07216878364870323f;   // 1/sqrt(192)
    float* sp = scores + (size_t)bh * S_ * S_;
#pragma unroll
    for (int ii = 0; ii < 4; ii++)
#pragma unroll
        for (int jj = 0; jj < 4; jj++)
            sp[(size_t)(i0 + ib + ii) * S_ + (j0 + jb + jj)] = acc[ii][jj] * inv;
}

// ---------------------------------------------------------------------------
// Row softmax with padding mask (in place on scores)
// ---------------------------------------------------------------------------
__global__ __launch_bounds__(256)
void softmax_kernel(float* __restrict__ scores, const int* __restrict__ mask)
{
    int row = blockIdx.x;                 // bh * S + i
    int b = row >> 14;
    float* sp = scores + (size_t)row * S_;
    const int* mp = mask + b * S_;
    int tid = threadIdx.x;

    __shared__ float red[256];

    float vals[4];
    float mx = -INFINITY;
#pragma unroll
    for (int u = 0; u < 4; u++) {
        int j = tid + u * 256;
        float v = sp[j];
        if (mp[j] == 1) v = -INFINITY;
        vals[u] = v;
        mx = fmaxf(mx, v);
    }
    red[tid] = mx; __syncthreads();
    for (int s = 128; s > 0; s >>= 1) {
        if (tid < s) red[tid] = fmaxf(red[tid], red[tid + s]);
        __syncthreads();
    }
    mx = red[0];
    __syncthreads();

    float sum = 0.f;
#pragma unroll
    for (int u = 0; u < 4; u++) {
        vals[u] = __expf(vals[u] - mx);
        sum += vals[u];
    }
    red[tid] = sum; __syncthreads();
    for (int s = 128; s > 0; s >>= 1) {
        if (tid < s) red[tid] += red[tid + s];
        __syncthreads();
    }
    float r = 1.f / red[0];
#pragma unroll
    for (int u = 0; u < 4; u++)
        sp[tid + u * 256] = vals[u] * r;
}

// ---------------------------------------------------------------------------
// AV: ctx[b, i, h*64+d] = sum_j attn[bh,i,j] * v[bh,j,d]
// ---------------------------------------------------------------------------
__global__ __launch_bounds__(256)
void av_kernel(const float* __restrict__ attn, const float* __restrict__ v,
               float* __restrict__ ctx)
{
    __shared__ float As[64][33];
    __shared__ float Bs[32][64];

    int bh = blockIdx.y;
    int i0 = blockIdx.x * 64;
    const float* ap = attn + (size_t)bh * S_ * S_;
    const float* vp = v    + (size_t)bh * S_ * DH_;
    int tid = threadIdx.x;
    int tx = tid & 15, ty = tid >> 4;
    int ib = ty * 4, jb = tx * 4;

    float acc[4][4];
#pragma unroll
    for (int a = 0; a < 4; a++)
#pragma unroll
        for (int b = 0; b < 4; b++) acc[a][b] = 0.f;

    for (int k0 = 0; k0 < S_; k0 += 32) {
        for (int f = tid; f < 64 * 8; f += 256) {
            int r = f >> 3, c = (f & 7) << 2;
            float4 x = *(const float4*)(ap + (size_t)(i0 + r) * S_ + k0 + c);
            As[r][c + 0] = x.x; As[r][c + 1] = x.y;
            As[r][c + 2] = x.z; As[r][c + 3] = x.w;
        }
        for (int f = tid; f < 32 * 16; f += 256) {
            int r = f >> 4, c = (f & 15) << 2;
            float4 x = *(const float4*)(vp + (size_t)(k0 + r) * DH_ + c);
            *(float4*)&Bs[r][c] = x;
        }
        __syncthreads();

#pragma unroll 8
        for (int kk = 0; kk < 32; kk++) {
            float avv[4], bvv[4];
#pragma unroll
            for (int ii = 0; ii < 4; ii++) avv[ii] = As[ib + ii][kk];
            float4 bq = *(const float4*)&Bs[kk][jb];
            bvv[0] = bq.x; bvv[1] = bq.y; bvv[2] = bq.z; bvv[3] = bq.w;
#pragma unroll
            for (int ii = 0; ii < 4; ii++)
#pragma unroll
                for (int jj = 0; jj < 4; jj++)
                    acc[ii][jj] += avv[ii] * bvv[jj];
        }
        __syncthreads();
    }

    int b = bh >> 4, h = bh & 15;
#pragma unroll
    for (int ii = 0; ii < 4; ii++)
#pragma unroll
        for (int jj = 0; jj < 4; jj++)
            ctx[((size_t)(b * S_ + i0 + ib + ii)) * D_ + h * DH_ + jb + jj] = acc[ii][jj];
}

// ---------------------------------------------------------------------------
// Launch
// ---------------------------------------------------------------------------
extern "C" void kernel_launch(void* const* d_in, const int* in_sizes, int n_in,
                              void* d_out, int out_size)
{
    const float* x    = (const float*)d_in[0];
    const float* rel  = (const float*)d_in[1];
    const int*   pmask= (const int*)  d_in[2];
    const float* Wq   = (const float*)d_in[3];
    const float* bq   = (const float*)d_in[4];
    const float* Wk   = (const float*)d_in[5];
    const float* bk   = (const float*)d_in[6];
    const float* Wv   = (const float*)d_in[7];
    const float* bv   = (const float*)d_in[8];
    const float* Wqr  = (const float*)d_in[9];
    const float* bqr  = (const float*)d_in[10];
    const float* Wkr  = (const float*)d_in[11];
    const float* bkr  = (const float*)d_in[12];
    const float* Wc   = (const float*)d_in[13];
    const float* bc   = (const float*)d_in[14];
    float* out = (float*)d_out;

    float *proj_base, *scores, *ctx;
    cudaGetSymbolAddress((void**)&proj_base, g_proj);
    cudaGetSymbolAddress((void**)&scores, g_scores);
    cudaGetSymbolAddress((void**)&ctx, g_ctx);

    const size_t P = (size_t)M_ * D_;
    float* q  = proj_base + 0 * P;
    float* k  = proj_base + 1 * P;
    float* v  = proj_base + 2 * P;
    float* qr = proj_base + 3 * P;
    float* kr = proj_base + 4 * P;

    const int SC_SMEM = (64 * 65 * 2 + 127 * 65 * 2) * 4;  // 99,320 bytes
    cudaFuncSetAttribute(scores_kernel,
                         cudaFuncAttributeMaxDynamicSharedMemorySize, SC_SMEM);

    dim3 gGemm(D_ / 128, M_ / 128);   // (8, 16)

    // 5 projections (tf32 tensor cores, scatter to (B,H,S,DH))
    gemm_tf32<<<gGemm, 256>>>(x,   Wq,  bq,  q,  D_, D_, 0);
    gemm_tf32<<<gGemm, 256>>>(x,   Wk,  bk,  k,  D_, D_, 0);
    gemm_tf32<<<gGemm, 256>>>(x,   Wv,  bv,  v,  D_, D_, 0);
    gemm_tf32<<<gGemm, 256>>>(rel, Wqr, bqr, qr, D_, D_, 0);
    gemm_tf32<<<gGemm, 256>>>(rel, Wkr, bkr, kr, D_, D_, 0);

    // fused disentangled scores
    dim3 gSc(S_ / 64, S_ / 64, BH_);
    scores_kernel<<<gSc, 256, SC_SMEM>>>(q, k, qr, kr, scores);

    // softmax + mask (in place)
    softmax_kernel<<<BH_ * S_, 256>>>(scores, pmask);

    // attn @ V -> ctx (B,S,D)
    dim3 gAv(S_ / 64, BH_);
    av_kernel<<<gAv, 256>>>(scores, v, ctx);

    // output projection (tf32 tensor cores)
    gemm_tf32<<<gGemm, 256>>>(ctx, Wc, bc, out, D_, D_, 1);
}

// round 3
// speedup vs baseline: 2.4959x; 1.5701x over previous
#include <cuda_runtime.h>
#include <math.h>
#include <stdint.h>

// Problem constants
#define B_  2
#define S_  1024
#define D_  1024
#define H_  16
#define DH_ 64
#define BH_ (B_ * H_)          // 32
#define M_  (B_ * S_)          // 2048

// ---------------------------------------------------------------------------
// Scratch
// ---------------------------------------------------------------------------
__device__ float g_proj[5ull * M_ * D_];          // q,k,v,qr,kr : 40MB
__device__ float g_ctx[(size_t)M_ * D_];          // 8MB

// ---------------------------------------------------------------------------
// helpers
// ---------------------------------------------------------------------------
__device__ __forceinline__ float to_tf32(float x) {
    uint32_t u = __float_as_uint(x);
    uint32_t y;
    asm("cvt.rna.tf32.f32 %0, %1;" : "=r"(y) : "r"(u));
    return __uint_as_float(y);
}

__device__ __forceinline__ void mma8(float* d, const uint32_t* a, const uint32_t* b) {
    asm volatile(
        "mma.sync.aligned.m16n8k8.row.col.f32.tf32.tf32.f32 "
        "{%0,%1,%2,%3}, {%4,%5,%6,%7}, {%8,%9}, {%0,%1,%2,%3};"
        : "+f"(d[0]), "+f"(d[1]), "+f"(d[2]), "+f"(d[3])
        : "r"(a[0]), "r"(a[1]), "r"(a[2]), "r"(a[3]),
          "r"(b[0]), "r"(b[1]));
}

// ---------------------------------------------------------------------------
// TF32 GEMM body (C = A * W^T + bias). 128x128 tile, BK=16, 256 threads.
// ---------------------------------------------------------------------------
__device__ __forceinline__
void gemm_body(const float* __restrict__ A, const float* __restrict__ W,
               const float* __restrict__ bias, float* __restrict__ C,
               int m0, int n0, int mode)
{
    __shared__ float As[128][20];
    __shared__ float Bs[128][20];

    int tid  = threadIdx.x;
    int warp = tid >> 5;
    int lane = tid & 31;
    int g    = lane >> 2;
    int tig  = lane & 3;
    int wm = warp >> 2;
    int wn = warp & 3;

    int lr  = tid >> 2;
    int lc4 = (tid & 3) << 2;

    float acc[4][4][4];
#pragma unroll
    for (int a = 0; a < 4; a++)
#pragma unroll
        for (int b = 0; b < 4; b++)
#pragma unroll
            for (int c = 0; c < 4; c++) acc[a][b][c] = 0.f;

    for (int k0 = 0; k0 < D_; k0 += 16) {
#pragma unroll
        for (int p = 0; p < 2; p++) {
            int r = lr + p * 64;
            float4 av = *(const float4*)(A + (size_t)(m0 + r) * D_ + k0 + lc4);
            float4 bv = *(const float4*)(W + (size_t)(n0 + r) * D_ + k0 + lc4);
            As[r][lc4 + 0] = to_tf32(av.x); As[r][lc4 + 1] = to_tf32(av.y);
            As[r][lc4 + 2] = to_tf32(av.z); As[r][lc4 + 3] = to_tf32(av.w);
            Bs[r][lc4 + 0] = to_tf32(bv.x); Bs[r][lc4 + 1] = to_tf32(bv.y);
            Bs[r][lc4 + 2] = to_tf32(bv.z); Bs[r][lc4 + 3] = to_tf32(bv.w);
        }
        __syncthreads();

#pragma unroll
        for (int ks = 0; ks < 16; ks += 8) {
            uint32_t af[4][4];
            uint32_t bf[4][2];
#pragma unroll
            for (int mt = 0; mt < 4; mt++) {
                int rb = wm * 64 + mt * 16;
                af[mt][0] = __float_as_uint(As[rb + g    ][ks + tig    ]);
                af[mt][1] = __float_as_uint(As[rb + g + 8][ks + tig    ]);
                af[mt][2] = __float_as_uint(As[rb + g    ][ks + tig + 4]);
                af[mt][3] = __float_as_uint(As[rb + g + 8][ks + tig + 4]);
            }
#pragma unroll
            for (int nt = 0; nt < 4; nt++) {
                int cb = wn * 32 + nt * 8;
                bf[nt][0] = __float_as_uint(Bs[cb + g][ks + tig    ]);
                bf[nt][1] = __float_as_uint(Bs[cb + g][ks + tig + 4]);
            }
#pragma unroll
            for (int mt = 0; mt < 4; mt++)
#pragma unroll
                for (int nt = 0; nt < 4; nt++)
                    mma8(acc[mt][nt], af[mt], bf[nt]);
        }
        __syncthreads();
    }

#pragma unroll
    for (int mt = 0; mt < 4; mt++)
#pragma unroll
        for (int nt = 0; nt < 4; nt++)
#pragma unroll
            for (int fr = 0; fr < 4; fr++) {
                int m = m0 + wm * 64 + mt * 16 + g + (fr >> 1) * 8;
                int n = n0 + wn * 32 + nt * 8 + tig * 2 + (fr & 1);
                float v = acc[mt][nt][fr] + bias[n];
                if (mode == 0) {
                    int b = m >> 10, s = m & 1023;
                    int h = n >> 6,  dh = n & 63;
                    C[(((size_t)(b * H_ + h) << 10) + s) * DH_ + dh] = v;
                } else {
                    C[(size_t)m * D_ + n] = v;
                }
            }
}

// 5 projections in one launch (z = which)
__global__ __launch_bounds__(256)
void proj_batched(const float* __restrict__ x, const float* __restrict__ rel,
                  const float* __restrict__ Wq,  const float* __restrict__ bq,
                  const float* __restrict__ Wk,  const float* __restrict__ bk,
                  const float* __restrict__ Wv,  const float* __restrict__ bv,
                  const float* __restrict__ Wqr, const float* __restrict__ bqr,
                  const float* __restrict__ Wkr, const float* __restrict__ bkr,
                  float* __restrict__ dst_base)
{
    int which = blockIdx.z;
    const float* A = (which < 3) ? x : rel;
    const float* W; const float* bias;
    switch (which) {
        case 0: W = Wq;  bias = bq;  break;
        case 1: W = Wk;  bias = bk;  break;
        case 2: W = Wv;  bias = bv;  break;
        case 3: W = Wqr; bias = bqr; break;
        default:W = Wkr; bias = bkr; break;
    }
    float* C = dst_base + (size_t)which * M_ * D_;
    gemm_body(A, W, bias, C, blockIdx.y * 128, blockIdx.x * 128, 0);
}

// output projection
__global__ __launch_bounds__(256)
void out_gemm(const float* __restrict__ A, const float* __restrict__ W,
              const float* __restrict__ bias, float* __restrict__ C)
{
    gemm_body(A, W, bias, C, blockIdx.y * 128, blockIdx.x * 128, 1);
}

// ---------------------------------------------------------------------------
// Fused flash attention with disentangled relative-position terms.
// Per CTA: head bh, 64-row i-tile. Loop over 16 j-tiles:
//   D1 = Q @ [K | KRg]^T  (64x192),  D2 = QRg @ K^T  (128x64)  [tensor cores]
//   s[i][j] = (D1[i][j] + D1[i][64+u] + D2[u][j]) / sqrt(192), u = i-j+63
//   online softmax -> P ;  O = O*alpha + P @ V  [tensor cores]
// ---------------------------------------------------------------------------
// smem float offsets
#define FQ   0          // Qs [64][68]
#define FK   4352       // Ks [64][68]
#define FV   8704       // Vs [64][68]
#define FKR  13056      // KRg [128][68]
#define FQR  21760      // QRg [128][68]
#define FD1  13056      // D1 [64][196]   (aliases KR/QR after MMA reads)
#define FD2  25600      // D2 [128][68]
#define FP   34304      // Ps [64][68]
#define FRB  38656      // rowbuf [64]
#define FMK  38720      // mask [64] ints
#define FLASH_SMEM_FLOATS 38784

__global__ __launch_bounds__(256)
void flash_kernel(const float* __restrict__ q, const float* __restrict__ k,
                  const float* __restrict__ v, const float* __restrict__ qr,
                  const float* __restrict__ kr, const int* __restrict__ mask,
                  float* __restrict__ ctx)
{
    extern __shared__ float sm[];
    float* Qs = sm + FQ;
    float* Ks = sm + FK;
    float* Vs = sm + FV;
    float* KR = sm + FKR;
    float* QR = sm + FQR;
    float* D1 = sm + FD1;
    float* D2 = sm + FD2;
    float* Ps = sm + FP;
    float* RB = sm + FRB;
    int*   MK = (int*)(sm + FMK);

    int tid  = threadIdx.x;
    int warp = tid >> 5, lane = tid & 31;
    int g = lane >> 2, tig = lane & 3;
    int wm  = warp >> 2, wn  = warp & 3;   // 2x4 grid (D1, O)
    int wm2 = warp >> 1, wn2 = warp & 1;   // 4x2 grid (D2)
    int tx = tid & 15, ty = tid >> 4;

    int bh = blockIdx.y;
    int i0 = blockIdx.x * 64;
    int b = bh >> 4, h = bh & 15;

    const float* qp  = q  + (size_t)bh * S_ * DH_;
    const float* kp  = k  + (size_t)bh * S_ * DH_;
    const float* vp  = v  + (size_t)bh * S_ * DH_;
    const float* qrp = qr + (size_t)bh * S_ * DH_;
    const float* krp = kr + (size_t)bh * S_ * DH_;
    const int*   mp  = mask + b * S_;

    // load Q once
    for (int f = tid; f < 64 * 16; f += 256) {
        int r = f >> 4, c = (f & 15) << 2;
        float4 t = *(const float4*)(qp + (size_t)(i0 + r) * DH_ + c);
        float* d = Qs + r * 68 + c;
        d[0] = to_tf32(t.x); d[1] = to_tf32(t.y);
        d[2] = to_tf32(t.z); d[3] = to_tf32(t.w);
    }

    float o[2][2][4];
#pragma unroll
    for (int a = 0; a < 2; a++)
#pragma unroll
        for (int c = 0; c < 2; c++)
#pragma unroll
            for (int f = 0; f < 4; f++) o[a][c][f] = 0.f;

    float m_r[4], l_r[4];
#pragma unroll
    for (int i = 0; i < 4; i++) { m_r[i] = -INFINITY; l_r[i] = 0.f; }

    const float inv = 0.07216878364870323f;   // 1/sqrt(192)

    for (int j0 = 0; j0 < S_; j0 += 64) {
        // ---- load K, V, gathered KR/QR, mask ----
        for (int f = tid; f < 64 * 16; f += 256) {
            int r = f >> 4, c = (f & 15) << 2;
            float4 t = *(const float4*)(kp + (size_t)(j0 + r) * DH_ + c);
            float* dk = Ks + r * 68 + c;
            dk[0] = to_tf32(t.x); dk[1] = to_tf32(t.y);
            dk[2] = to_tf32(t.z); dk[3] = to_tf32(t.w);
            float4 u = *(const float4*)(vp + (size_t)(j0 + r) * DH_ + c);
            float* dv = Vs + r * 68 + c;
            dv[0] = to_tf32(u.x); dv[1] = to_tf32(u.y);
            dv[2] = to_tf32(u.z); dv[3] = to_tf32(u.w);
        }
        int p0 = i0 - j0 + 449;
        for (int f = tid; f < 128 * 16; f += 256) {
            int t = f >> 4, c = (f & 15) << 2;
            float* dk = KR + t * 68 + c;
            float* dq = QR + t * 68 + c;
            if (t < 127) {
                int pr = p0 + t;
                pr = pr < 0 ? 0 : (pr > 1023 ? 1023 : pr);
                float4 a = *(const float4*)(krp + (size_t)pr * DH_ + c);
                dk[0] = to_tf32(a.x); dk[1] = to_tf32(a.y);
                dk[2] = to_tf32(a.z); dk[3] = to_tf32(a.w);
                float4 bb = *(const float4*)(qrp + (size_t)pr * DH_ + c);
                dq[0] = to_tf32(bb.x); dq[1] = to_tf32(bb.y);
                dq[2] = to_tf32(bb.z); dq[3] = to_tf32(bb.w);
            } else {
                dk[0] = dk[1] = dk[2] = dk[3] = 0.f;
                dq[0] = dq[1] = dq[2] = dq[3] = 0.f;
            }
        }
        if (tid < 64) MK[tid] = mp[j0 + tid];
        __syncthreads();

        // ---- phase A: D1 = Q @ [K | KR]^T (64 x 192) ----
        float d1[2][6][4];
#pragma unroll
        for (int a = 0; a < 2; a++)
#pragma unroll
            for (int c = 0; c < 6; c++)
#pragma unroll
                for (int f = 0; f < 4; f++) d1[a][c][f] = 0.f;

        const float* bpA[6];
#pragma unroll
        for (int nt = 0; nt < 6; nt++) {
            int c = wn * 48 + nt * 8 + g;
            bpA[nt] = (c < 64) ? (Ks + c * 68) : (KR + (c - 64) * 68);
        }
#pragma unroll
        for (int ks = 0; ks < 64; ks += 8) {
            uint32_t af[2][4], bf[6][2];
#pragma unroll
            for (int mt = 0; mt < 2; mt++) {
                int rb = wm * 32 + mt * 16;
                af[mt][0] = __float_as_uint(Qs[(rb + g    ) * 68 + ks + tig    ]);
                af[mt][1] = __float_as_uint(Qs[(rb + g + 8) * 68 + ks + tig    ]);
                af[mt][2] = __float_as_uint(Qs[(rb + g    ) * 68 + ks + tig + 4]);
                af[mt][3] = __float_as_uint(Qs[(rb + g + 8) * 68 + ks + tig + 4]);
            }
#pragma unroll
            for (int nt = 0; nt < 6; nt++) {
                bf[nt][0] = __float_as_uint(bpA[nt][ks + tig    ]);
                bf[nt][1] = __float_as_uint(bpA[nt][ks + tig + 4]);
            }
#pragma unroll
            for (int mt = 0; mt < 2; mt++)
#pragma unroll
                for (int nt = 0; nt < 6; nt++)
                    mma8(d1[mt][nt], af[mt], bf[nt]);
        }

        // ---- phase B: D2 = QR @ K^T (128 x 64) ----
        float d2[2][4][4];
#pragma unroll
        for (int a = 0; a < 2; a++)
#pragma unroll
            for (int c = 0; c < 4; c++)
#pragma unroll
                for (int f = 0; f < 4; f++) d2[a][c][f] = 0.f;
#pragma unroll
        for (int ks = 0; ks < 64; ks += 8) {
            uint32_t af[2][4], bf[4][2];
#pragma unroll
            for (int mt = 0; mt < 2; mt++) {
                int rb = wm2 * 32 + mt * 16;
                af[mt][0] = __float_as_uint(QR[(rb + g    ) * 68 + ks + tig    ]);
                af[mt][1] = __float_as_uint(QR[(rb + g + 8) * 68 + ks + tig    ]);
                af[mt][2] = __float_as_uint(QR[(rb + g    ) * 68 + ks + tig + 4]);
                af[mt][3] = __float_as_uint(QR[(rb + g + 8) * 68 + ks + tig + 4]);
            }
#pragma unroll
            for (int nt = 0; nt < 4; nt++) {
                int c = wn2 * 32 + nt * 8 + g;
                bf[nt][0] = __float_as_uint(Ks[c * 68 + ks + tig    ]);
                bf[nt][1] = __float_as_uint(Ks[c * 68 + ks + tig + 4]);
            }
#pragma unroll
            for (int mt = 0; mt < 2; mt++)
#pragma unroll
                for (int nt = 0; nt < 4; nt++)
                    mma8(d2[mt][nt], af[mt], bf[nt]);
        }
        __syncthreads();   // all KR/QR/Ks reads complete

        // ---- write D1, D2 to smem (aliases KR/QR) ----
#pragma unroll
        for (int mt = 0; mt < 2; mt++)
#pragma unroll
            for (int nt = 0; nt < 6; nt++)
#pragma unroll
                for (int fr = 0; fr < 4; fr++) {
                    int r = wm * 32 + mt * 16 + g + (fr >> 1) * 8;
                    int c = wn * 48 + nt * 8 + tig * 2 + (fr & 1);
                    D1[r * 196 + c] = d1[mt][nt][fr];
                }
#pragma unroll
        for (int mt = 0; mt < 2; mt++)
#pragma unroll
            for (int nt = 0; nt < 4; nt++)
#pragma unroll
                for (int fr = 0; fr < 4; fr++) {
                    int r = wm2 * 32 + mt * 16 + g + (fr >> 1) * 8;
                    int c = wn2 * 32 + nt * 8 + tig * 2 + (fr & 1);
                    D2[r * 68 + c] = d2[mt][nt][fr];
                }
        __syncthreads();

        // ---- epilogue: combine terms + online softmax -> P, alpha ----
#pragma unroll
        for (int ii = 0; ii < 4; ii++) {
            int r = ty * 4 + ii;
            float pv[4];
            float rmax = -INFINITY;
#pragma unroll
            for (int jj = 0; jj < 4; jj++) {
                int c = tx * 4 + jj;
                int u = r - c + 63;
                float val = (D1[r * 196 + c] + D1[r * 196 + 64 + u]
                             + D2[u * 68 + c]) * inv;
                if (MK[c]) val = -INFINITY;
                pv[jj] = val;
                rmax = fmaxf(rmax, val);
            }
            rmax = fmaxf(rmax, __shfl_xor_sync(0xffffffffu, rmax, 1));
            rmax = fmaxf(rmax, __shfl_xor_sync(0xffffffffu, rmax, 2));
            rmax = fmaxf(rmax, __shfl_xor_sync(0xffffffffu, rmax, 4));
            rmax = fmaxf(rmax, __shfl_xor_sync(0xffffffffu, rmax, 8));
            float mnew = fmaxf(m_r[ii], rmax);
            float al = __expf(m_r[ii] - mnew);
            m_r[ii] = mnew;
            float rsum = 0.f;
#pragma unroll
            for (int jj = 0; jj < 4; jj++) {
                pv[jj] = __expf(pv[jj] - mnew);
                rsum += pv[jj];
            }
            rsum += __shfl_xor_sync(0xffffffffu, rsum, 1);
            rsum += __shfl_xor_sync(0xffffffffu, rsum, 2);
            rsum += __shfl_xor_sync(0xffffffffu, rsum, 4);
            rsum += __shfl_xor_sync(0xffffffffu, rsum, 8);
            l_r[ii] = l_r[ii] * al + rsum;

            float* pd = Ps + r * 68 + tx * 4;
            pd[0] = to_tf32(pv[0]); pd[1] = to_tf32(pv[1]);
            pd[2] = to_tf32(pv[2]); pd[3] = to_tf32(pv[3]);
            if (tx == 0) RB[r] = al;
        }
        __syncthreads();

        // ---- phase C: O = O*alpha + P @ V ----
#pragma unroll
        for (int mt = 0; mt < 2; mt++) {
            int rb = wm * 32 + mt * 16;
            float ag  = RB[rb + g];
            float ag8 = RB[rb + g + 8];
#pragma unroll
            for (int nt = 0; nt < 2; nt++) {
                o[mt][nt][0] *= ag;  o[mt][nt][1] *= ag;
                o[mt][nt][2] *= ag8; o[mt][nt][3] *= ag8;
            }
        }
#pragma unroll
        for (int ks = 0; ks < 64; ks += 8) {
            uint32_t af[2][4], bf[2][2];
#pragma unroll
            for (int mt = 0; mt < 2; mt++) {
                int rb = wm * 32 + mt * 16;
                af[mt][0] = __float_as_uint(Ps[(rb + g    ) * 68 + ks + tig    ]);
                af[mt][1] = __float_as_uint(Ps[(rb + g + 8) * 68 + ks + tig    ]);
                af[mt][2] = __float_as_uint(Ps[(rb + g    ) * 68 + ks + tig + 4]);
                af[mt][3] = __float_as_uint(Ps[(rb + g + 8) * 68 + ks + tig + 4]);
            }
#pragma unroll
            for (int nt = 0; nt < 2; nt++) {
                int cb = wn * 16 + nt * 8 + g;
                bf[nt][0] = __float_as_uint(Vs[(ks + tig    ) * 68 + cb]);
                bf[nt][1] = __float_as_uint(Vs[(ks + tig + 4) * 68 + cb]);
            }
#pragma unroll
            for (int mt = 0; mt < 2; mt++)
#pragma unroll
                for (int nt = 0; nt < 2; nt++)
                    mma8(o[mt][nt], af[mt], bf[nt]);
        }
        __syncthreads();
    }

    // ---- finalize: O /= l, write ctx in (B,S,D) layout ----
    if (tx == 0) {
#pragma unroll
        for (int ii = 0; ii < 4; ii++) RB[ty * 4 + ii] = l_r[ii];
    }
    __syncthreads();

#pragma unroll
    for (int mt = 0; mt < 2; mt++) {
        int rb = wm * 32 + mt * 16;
        float rg  = 1.f / RB[rb + g];
        float rg8 = 1.f / RB[rb + g + 8];
#pragma unroll
        for (int nt = 0; nt < 2; nt++)
#pragma unroll
            for (int fr = 0; fr < 4; fr++) {
                int r = rb + g + (fr >> 1) * 8;
                int c = wn * 16 + nt * 8 + tig * 2 + (fr & 1);
                float val = o[mt][nt][fr] * ((fr < 2) ? rg : rg8);
                ctx[((size_t)(b * S_ + i0 + r)) * D_ + h * DH_ + c] = val;
            }
    }
}

// ---------------------------------------------------------------------------
// Launch
// ---------------------------------------------------------------------------
extern "C" void kernel_launch(void* const* d_in, const int* in_sizes, int n_in,
                              void* d_out, int out_size)
{
    const float* x    = (const float*)d_in[0];
    const float* rel  = (const float*)d_in[1];
    const int*   pmask= (const int*)  d_in[2];
    const float* Wq   = (const float*)d_in[3];
    const float* bq   = (const float*)d_in[4];
    const float* Wk   = (const float*)d_in[5];
    const float* bk   = (const float*)d_in[6];
    const float* Wv   = (const float*)d_in[7];
    const float* bv   = (const float*)d_in[8];
    const float* Wqr  = (const float*)d_in[9];
    const float* bqr  = (const float*)d_in[10];
    const float* Wkr  = (const float*)d_in[11];
    const float* bkr  = (const float*)d_in[12];
    const float* Wc   = (const float*)d_in[13];
    const float* bc   = (const float*)d_in[14];
    float* out = (float*)d_out;

    float *proj_base, *ctx;
    cudaGetSymbolAddress((void**)&proj_base, g_proj);
    cudaGetSymbolAddress((void**)&ctx, g_ctx);

    const size_t P = (size_t)M_ * D_;
    float* q  = proj_base + 0 * P;
    float* k  = proj_base + 1 * P;
    float* v  = proj_base + 2 * P;
    float* qr = proj_base + 3 * P;
    float* kr = proj_base + 4 * P;

    const int FLASH_SMEM = FLASH_SMEM_FLOATS * 4;   // 155,136 bytes
    cudaFuncSetAttribute(flash_kernel,
                         cudaFuncAttributeMaxDynamicSharedMemorySize, FLASH_SMEM);

    // 5 projections, one launch
    dim3 gProj(D_ / 128, M_ / 128, 5);   // (8,16,5)
    proj_batched<<<gProj, 256>>>(x, rel, Wq, bq, Wk, bk, Wv, bv,
                                 Wqr, bqr, Wkr, bkr, proj_base);

    // fused scores+softmax+AV
    dim3 gF(S_ / 64, BH_);               // (16,32)
    flash_kernel<<<gF, 256, FLASH_SMEM>>>(q, k, v, qr, kr, pmask, ctx);

    // output projection
    dim3 gGemm(D_ / 128, M_ / 128);
    out_gemm<<<gGemm, 256>>>(ctx, Wc, bc, out);
}